// round 6
// baseline (speedup 1.0000x reference)
#include <cuda_runtime.h>
#include <math.h>
#include <stdint.h>

#define Dv   512
#define Nn   8192
#define K1   2560    // 5*D  (Agg_0..3, x)
#define QK   2048    // 4*D  (q,k,v,skip)

// ---- static scratch (no allocations allowed) ----
__device__ float g_H0[(size_t)Nn * K1];     // 80 MB  [N, 5D]
__device__ float g_ho[(size_t)Nn * Dv];     // 16 MB  [N, D]
__device__ float g_qkvs[(size_t)Nn * QK];   // 64 MB  [N, 4, D] = q|k|v|skip

__device__ __forceinline__ int lower_bound_i(const int* __restrict__ a, int n, int key) {
    int lo = 0, hi = n;
    while (lo < hi) { int m = (lo + hi) >> 1; if (a[m] < key) lo = m + 1; else hi = m; }
    return lo;
}

__device__ __forceinline__ float tf32r(float x) {
    uint32_t y;
    asm("cvt.rna.tf32.f32 %0, %1;" : "=r"(y) : "f"(x));
    return __uint_as_float(y);
}

__device__ __forceinline__ void mma8(float* d, const uint32_t* a, const uint32_t* b) {
    asm volatile(
        "mma.sync.aligned.m16n8k8.row.col.f32.tf32.tf32.f32 "
        "{%0,%1,%2,%3}, {%4,%5,%6,%7}, {%8,%9}, {%0,%1,%2,%3};"
        : "+f"(d[0]), "+f"(d[1]), "+f"(d[2]), "+f"(d[3])
        : "r"(a[0]), "r"(a[1]), "r"(a[2]), "r"(a[3]), "r"(b[0]), "r"(b[1]));
}

// ============================================================
// Kernel 1: per-node per-relation neighbor mean -> H0 [N, 5D]
// ============================================================
__global__ __launch_bounds__(128) void agg_kernel(
    const float* __restrict__ x,
    const int*   __restrict__ src,
    const int*   __restrict__ dst,
    const int*   __restrict__ et,
    int E)
{
    int i = blockIdx.x;
    int t = threadIdx.x;
    __shared__ int s_lo, s_nE;
    __shared__ int s_src[32], s_rel[32];
    __shared__ int s_cnt[4];

    if (t == 0) {
        int lo = lower_bound_i(dst, E, i);
        int hi = lower_bound_i(dst, E, i + 1);
        s_lo = lo;
        int n = hi - lo; if (n > 32) n = 32;
        s_nE = n;
    }
    if (t < 4) s_cnt[t] = 0;
    __syncthreads();
    int nE = s_nE, lo = s_lo;
    if (t < nE) {
        s_src[t] = src[lo + t];
        int r = et[lo + t];
        s_rel[t] = r;
        atomicAdd(&s_cnt[r], 1);
    }
    __syncthreads();

    int d0 = t * 4;
    float4 a0 = {0,0,0,0}, a1 = a0, a2 = a0, a3 = a0;
    for (int e = 0; e < nE; e++) {
        int s = s_src[e];
        float4 v = *reinterpret_cast<const float4*>(x + (size_t)s * Dv + d0);
        int r = s_rel[e];
        if (r == 0)      { a0.x += v.x; a0.y += v.y; a0.z += v.z; a0.w += v.w; }
        else if (r == 1) { a1.x += v.x; a1.y += v.y; a1.z += v.z; a1.w += v.w; }
        else if (r == 2) { a2.x += v.x; a2.y += v.y; a2.z += v.z; a2.w += v.w; }
        else             { a3.x += v.x; a3.y += v.y; a3.z += v.z; a3.w += v.w; }
    }
    float i0 = 1.f / fmaxf((float)s_cnt[0], 1.f);
    float i1 = 1.f / fmaxf((float)s_cnt[1], 1.f);
    float i2 = 1.f / fmaxf((float)s_cnt[2], 1.f);
    float i3 = 1.f / fmaxf((float)s_cnt[3], 1.f);
    float* H = g_H0 + (size_t)i * K1;
    a0.x*=i0; a0.y*=i0; a0.z*=i0; a0.w*=i0;
    a1.x*=i1; a1.y*=i1; a1.z*=i1; a1.w*=i1;
    a2.x*=i2; a2.y*=i2; a2.z*=i2; a2.w*=i2;
    a3.x*=i3; a3.y*=i3; a3.z*=i3; a3.w*=i3;
    *reinterpret_cast<float4*>(H + 0*Dv + d0) = a0;
    *reinterpret_cast<float4*>(H + 1*Dv + d0) = a1;
    *reinterpret_cast<float4*>(H + 2*Dv + d0) = a2;
    *reinterpret_cast<float4*>(H + 3*Dv + d0) = a3;
    float4 xv = *reinterpret_cast<const float4*>(x + (size_t)i * Dv + d0);
    *reinterpret_cast<float4*>(H + 4*Dv + d0) = xv;
}

// ============================================================
// TF32 tensor-core GEMM tiles: 128x128x32, 8 warps (2x4),
// warp tile 64x32 via m16n8k8 mma.
// As layout [m][k], lead 36 (frag reads bank-conflict-free).
// Bs layout [k][n], lead 132 (frag reads bank-conflict-free).
// ============================================================
#define LDA 36
#define LDB 132

// Kernel 2: ho = H0 [8192x2560] @ [W_rel;W_root] [2560x512] + b
__global__ __launch_bounds__(256) void gemm_rgcn(
    const float* __restrict__ Wrel,   // [2048, 512]
    const float* __restrict__ Wroot,  // [512, 512]
    const float* __restrict__ bias)   // [512]
{
    __shared__ float As[128 * LDA];
    __shared__ float Bs[32 * LDB];
    const float* A = g_H0;
    float* C = g_ho;
    const int K = K1;
    int tid = threadIdx.x;
    int n0 = blockIdx.x * 128, m0 = blockIdx.y * 128;
    int wid = tid >> 5, lane = tid & 31;
    int wr = wid >> 2, wc = wid & 3;
    int g = lane >> 2, tig = lane & 3;
    float acc[4][4][4] = {};
    float4 ra[4], rb[4];

    #pragma unroll
    for (int s = 0; s < 4; s++) {
        int idx = tid + 256 * s;
        int m = idx >> 3, kq = (idx & 7) * 4;
        ra[s] = *(const float4*)(A + (size_t)(m0 + m) * K + kq);
    }
    #pragma unroll
    for (int s = 0; s < 4; s++) {
        int idx = tid + 256 * s;
        int k = idx >> 5, n4 = (idx & 31) * 4;
        rb[s] = *(const float4*)(Wrel + (size_t)k * Dv + n0 + n4);
    }

    const int ITER = K / 32;
    for (int it = 0; it < ITER; ++it) {
        #pragma unroll
        for (int s = 0; s < 4; s++) {
            int idx = tid + 256 * s;
            int m = idx >> 3, kq = (idx & 7) * 4;
            float* p = &As[m * LDA + kq];
            p[0] = tf32r(ra[s].x); p[1] = tf32r(ra[s].y);
            p[2] = tf32r(ra[s].z); p[3] = tf32r(ra[s].w);
        }
        #pragma unroll
        for (int s = 0; s < 4; s++) {
            int idx = tid + 256 * s;
            int k = idx >> 5, n4 = (idx & 31) * 4;
            float* p = &Bs[k * LDB + n4];
            p[0] = tf32r(rb[s].x); p[1] = tf32r(rb[s].y);
            p[2] = tf32r(rb[s].z); p[3] = tf32r(rb[s].w);
        }
        __syncthreads();
        if (it + 1 < ITER) {
            int k0n = (it + 1) * 32;
            #pragma unroll
            for (int s = 0; s < 4; s++) {
                int idx = tid + 256 * s;
                int m = idx >> 3, kq = (idx & 7) * 4;
                ra[s] = *(const float4*)(A + (size_t)(m0 + m) * K + k0n + kq);
            }
            #pragma unroll
            for (int s = 0; s < 4; s++) {
                int idx = tid + 256 * s;
                int k = idx >> 5, n4 = (idx & 31) * 4;
                int kk = k0n + k;
                const float* bp = (kk < 2048) ? (Wrel + (size_t)kk * Dv)
                                              : (Wroot + (size_t)(kk - 2048) * Dv);
                rb[s] = *(const float4*)(bp + n0 + n4);
            }
        }
        #pragma unroll
        for (int ks = 0; ks < 4; ks++) {
            int kb = ks * 8;
            uint32_t af[4][4], bf[4][2];
            #pragma unroll
            for (int mt = 0; mt < 4; mt++) {
                int mr = wr * 64 + mt * 16;
                af[mt][0] = __float_as_uint(As[(mr + g)     * LDA + kb + tig]);
                af[mt][1] = __float_as_uint(As[(mr + g + 8) * LDA + kb + tig]);
                af[mt][2] = __float_as_uint(As[(mr + g)     * LDA + kb + tig + 4]);
                af[mt][3] = __float_as_uint(As[(mr + g + 8) * LDA + kb + tig + 4]);
            }
            #pragma unroll
            for (int nt = 0; nt < 4; nt++) {
                int nc = wc * 32 + nt * 8;
                bf[nt][0] = __float_as_uint(Bs[(kb + tig)     * LDB + nc + g]);
                bf[nt][1] = __float_as_uint(Bs[(kb + tig + 4) * LDB + nc + g]);
            }
            #pragma unroll
            for (int mt = 0; mt < 4; mt++)
                #pragma unroll
                for (int nt = 0; nt < 4; nt++)
                    mma8(acc[mt][nt], af[mt], bf[nt]);
        }
        __syncthreads();
    }
    #pragma unroll
    for (int mt = 0; mt < 4; mt++) {
        int mr = m0 + wr * 64 + mt * 16;
        #pragma unroll
        for (int nt = 0; nt < 4; nt++) {
            int nc = n0 + wc * 32 + nt * 8 + 2 * tig;
            float b0 = bias[nc], b1 = bias[nc + 1];
            float2 v0 = {acc[mt][nt][0] + b0, acc[mt][nt][1] + b1};
            float2 v1 = {acc[mt][nt][2] + b0, acc[mt][nt][3] + b1};
            *(float2*)(C + (size_t)(mr + g)     * Dv + nc) = v0;
            *(float2*)(C + (size_t)(mr + g + 8) * Dv + nc) = v1;
        }
    }
}

// Kernel 3: [q|k|v|skip] = ho [8192x512] @ W [512x2048] + b
__global__ __launch_bounds__(256) void gemm_qkvs(
    const float* __restrict__ Wq, const float* __restrict__ Wk,
    const float* __restrict__ Wv, const float* __restrict__ Ws,
    const float* __restrict__ bq, const float* __restrict__ bk,
    const float* __restrict__ bv, const float* __restrict__ bs)
{
    __shared__ float As[128 * LDA];
    __shared__ float Bs[32 * LDB];
    const float* A = g_ho;
    float* C = g_qkvs;
    const int K = Dv;
    int tid = threadIdx.x;
    int n0 = blockIdx.x * 128, m0 = blockIdx.y * 128;
    int wsel = n0 >> 9;
    const float* W  = (wsel == 0) ? Wq : (wsel == 1) ? Wk : (wsel == 2) ? Wv : Ws;
    const float* bb = (wsel == 0) ? bq : (wsel == 1) ? bk : (wsel == 2) ? bv : bs;
    int bc0 = n0 & 511;
    int wid = tid >> 5, lane = tid & 31;
    int wr = wid >> 2, wc = wid & 3;
    int g = lane >> 2, tig = lane & 3;
    float acc[4][4][4] = {};
    float4 ra[4], rb[4];

    #pragma unroll
    for (int s = 0; s < 4; s++) {
        int idx = tid + 256 * s;
        int m = idx >> 3, kq = (idx & 7) * 4;
        ra[s] = *(const float4*)(A + (size_t)(m0 + m) * K + kq);
    }
    #pragma unroll
    for (int s = 0; s < 4; s++) {
        int idx = tid + 256 * s;
        int k = idx >> 5, n4 = (idx & 31) * 4;
        rb[s] = *(const float4*)(W + (size_t)k * Dv + bc0 + n4);
    }

    const int ITER = K / 32;   // 16
    for (int it = 0; it < ITER; ++it) {
        #pragma unroll
        for (int s = 0; s < 4; s++) {
            int idx = tid + 256 * s;
            int m = idx >> 3, kq = (idx & 7) * 4;
            float* p = &As[m * LDA + kq];
            p[0] = tf32r(ra[s].x); p[1] = tf32r(ra[s].y);
            p[2] = tf32r(ra[s].z); p[3] = tf32r(ra[s].w);
        }
        #pragma unroll
        for (int s = 0; s < 4; s++) {
            int idx = tid + 256 * s;
            int k = idx >> 5, n4 = (idx & 31) * 4;
            float* p = &Bs[k * LDB + n4];
            p[0] = tf32r(rb[s].x); p[1] = tf32r(rb[s].y);
            p[2] = tf32r(rb[s].z); p[3] = tf32r(rb[s].w);
        }
        __syncthreads();
        if (it + 1 < ITER) {
            int k0n = (it + 1) * 32;
            #pragma unroll
            for (int s = 0; s < 4; s++) {
                int idx = tid + 256 * s;
                int m = idx >> 3, kq = (idx & 7) * 4;
                ra[s] = *(const float4*)(A + (size_t)(m0 + m) * K + k0n + kq);
            }
            #pragma unroll
            for (int s = 0; s < 4; s++) {
                int idx = tid + 256 * s;
                int k = idx >> 5, n4 = (idx & 31) * 4;
                rb[s] = *(const float4*)(W + (size_t)(k0n + k) * Dv + bc0 + n4);
            }
        }
        #pragma unroll
        for (int ks = 0; ks < 4; ks++) {
            int kb = ks * 8;
            uint32_t af[4][4], bf[4][2];
            #pragma unroll
            for (int mt = 0; mt < 4; mt++) {
                int mr = wr * 64 + mt * 16;
                af[mt][0] = __float_as_uint(As[(mr + g)     * LDA + kb + tig]);
                af[mt][1] = __float_as_uint(As[(mr + g + 8) * LDA + kb + tig]);
                af[mt][2] = __float_as_uint(As[(mr + g)     * LDA + kb + tig + 4]);
                af[mt][3] = __float_as_uint(As[(mr + g + 8) * LDA + kb + tig + 4]);
            }
            #pragma unroll
            for (int nt = 0; nt < 4; nt++) {
                int nc = wc * 32 + nt * 8;
                bf[nt][0] = __float_as_uint(Bs[(kb + tig)     * LDB + nc + g]);
                bf[nt][1] = __float_as_uint(Bs[(kb + tig + 4) * LDB + nc + g]);
            }
            #pragma unroll
            for (int mt = 0; mt < 4; mt++)
                #pragma unroll
                for (int nt = 0; nt < 4; nt++)
                    mma8(acc[mt][nt], af[mt], bf[nt]);
        }
        __syncthreads();
    }
    #pragma unroll
    for (int mt = 0; mt < 4; mt++) {
        int mr = m0 + wr * 64 + mt * 16;
        #pragma unroll
        for (int nt = 0; nt < 4; nt++) {
            int colw = wc * 32 + nt * 8 + 2 * tig;
            int nc = n0 + colw;            // global col in [0,2048)
            int bi = bc0 + colw;           // index into 512-wide bias
            float b0 = bb[bi], b1 = bb[bi + 1];
            float2 v0 = {acc[mt][nt][0] + b0, acc[mt][nt][1] + b1};
            float2 v1 = {acc[mt][nt][2] + b0, acc[mt][nt][3] + b1};
            *(float2*)(C + (size_t)(mr + g)     * QK + nc) = v0;
            *(float2*)(C + (size_t)(mr + g + 8) * QK + nc) = v1;
        }
    }
}

// ============================================================
// Kernel 4: per-node attention softmax + skip + leaky + residual + LN
// ============================================================
__global__ __launch_bounds__(256) void attn_kernel(
    const float* __restrict__ x,
    const int*   __restrict__ src,
    const int*   __restrict__ dst,
    int E,
    const float* __restrict__ gamma,
    const float* __restrict__ beta,
    float* __restrict__ out)
{
    int i = blockIdx.x;
    int t = threadIdx.x;
    __shared__ float q_s[512];
    __shared__ float logit[32];
    __shared__ float alpha[32];
    __shared__ int   s_src[32];
    __shared__ int   s_lo, s_nE;
    __shared__ float red1[8], red2[8];
    __shared__ float s_mu, s_rstd;
    const float* qkvs = g_qkvs;

    if (t == 0) {
        int lo = lower_bound_i(dst, E, i);
        int hi = lower_bound_i(dst, E, i + 1);
        s_lo = lo; int n = hi - lo; if (n > 32) n = 32; s_nE = n;
    }
    __syncthreads();
    int nE = s_nE, lo = s_lo;
    q_s[t]       = qkvs[(size_t)i * QK + t];
    q_s[t + 256] = qkvs[(size_t)i * QK + t + 256];
    if (t < nE) s_src[t] = src[lo + t];
    __syncthreads();

    int wid = t >> 5, lane = t & 31;
    for (int e = wid; e < nE; e += 8) {
        const float* kp = qkvs + (size_t)s_src[e] * QK + 512;
        float sum = 0.f;
        #pragma unroll
        for (int c = 0; c < 4; c++) {
            int d = c * 128 + lane * 4;
            float4 qa = *(const float4*)&q_s[d];
            float4 kb = *(const float4*)(kp + d);
            sum += qa.x*kb.x + qa.y*kb.y + qa.z*kb.z + qa.w*kb.w;
        }
        #pragma unroll
        for (int o = 16; o; o >>= 1) sum += __shfl_xor_sync(0xffffffffu, sum, o);
        if (lane == 0) logit[e] = sum * 0.04419417382415922f; // 1/sqrt(512)
    }
    __syncthreads();
    if (t == 0) {
        float mx = -INFINITY;
        for (int e = 0; e < nE; e++) mx = fmaxf(mx, logit[e]);
        if (nE == 0 || !isfinite(mx)) mx = 0.f;
        float den = 0.f;
        for (int e = 0; e < nE; e++) { float ex = expf(logit[e] - mx); alpha[e] = ex; den += ex; }
        float inv = 1.f / fmaxf(den, 1e-16f);
        for (int e = 0; e < nE; e++) alpha[e] *= inv;
    }
    __syncthreads();

    int d0 = t * 2;
    float acc0 = 0.f, acc1 = 0.f;
    for (int e = 0; e < nE; e++) {
        float a = alpha[e];
        float2 v = *(const float2*)(qkvs + (size_t)s_src[e] * QK + 1024 + d0);
        acc0 += a * v.x; acc1 += a * v.y;
    }
    float2 sk = *(const float2*)(qkvs + (size_t)i * QK + 1536 + d0);
    float h0 = acc0 + sk.x, h1 = acc1 + sk.y;
    h0 = h0 > 0.f ? h0 : 0.01f * h0;
    h1 = h1 > 0.f ? h1 : 0.01f * h1;
    float2 xv = *(const float2*)(x + (size_t)i * Dv + d0);
    float o0 = xv.x + h0, o1 = xv.y + h1;

    float s1 = o0 + o1, s2 = o0*o0 + o1*o1;
    #pragma unroll
    for (int o = 16; o; o >>= 1) {
        s1 += __shfl_xor_sync(0xffffffffu, s1, o);
        s2 += __shfl_xor_sync(0xffffffffu, s2, o);
    }
    if (lane == 0) { red1[wid] = s1; red2[wid] = s2; }
    __syncthreads();
    if (t == 0) {
        float S1 = 0.f, S2 = 0.f;
        #pragma unroll
        for (int w = 0; w < 8; w++) { S1 += red1[w]; S2 += red2[w]; }
        float mu = S1 / 512.f;
        float var = S2 / 512.f - mu * mu;
        s_mu = mu; s_rstd = rsqrtf(var + 1e-5f);
    }
    __syncthreads();
    float mu = s_mu, rs = s_rstd;
    float2 ov;
    ov.x = (o0 - mu) * rs * gamma[d0]     + beta[d0];
    ov.y = (o1 - mu) * rs * gamma[d0 + 1] + beta[d0 + 1];
    *(float2*)(out + (size_t)i * Dv + d0) = ov;
}

// scalar loss output (always 0 in eval path)
__global__ void tail_kernel(float* out, int out_size) {
    int idx = Nn * Dv + threadIdx.x;
    if (idx < out_size) out[idx] = 0.f;
}

extern "C" void kernel_launch(void* const* d_in, const int* in_sizes, int n_in,
                              void* d_out, int out_size) {
    const float* x     = (const float*)d_in[0];
    const int*   ei    = (const int*)  d_in[1];
    const int*   et    = (const int*)  d_in[2];
    const float* Wrel  = (const float*)d_in[3];
    const float* Wroot = (const float*)d_in[4];
    const float* brg   = (const float*)d_in[5];
    const float* Wq    = (const float*)d_in[6];
    const float* bq    = (const float*)d_in[7];
    const float* Wk    = (const float*)d_in[8];
    const float* bk    = (const float*)d_in[9];
    const float* Wv    = (const float*)d_in[10];
    const float* bv    = (const float*)d_in[11];
    const float* Wsk   = (const float*)d_in[12];
    const float* bsk   = (const float*)d_in[13];
    const float* gamma = (const float*)d_in[14];
    const float* beta  = (const float*)d_in[15];
    float* out = (float*)d_out;

    int E = in_sizes[2];
    const int* src = ei;
    const int* dst = ei + E;

    agg_kernel<<<Nn, 128>>>(x, src, dst, et, E);
    gemm_rgcn<<<dim3(Dv / 128, Nn / 128), 256>>>(Wrel, Wroot, brg);
    gemm_qkvs<<<dim3(QK / 128, Nn / 128), 256>>>(Wq, Wk, Wv, Wsk, bq, bk, bv, bsk);
    attn_kernel<<<Nn, 256>>>(x, src, dst, E, gamma, beta, out);
    if (out_size > Nn * Dv) tail_kernel<<<1, 256>>>(out, out_size);
}

// round 7
// speedup vs baseline: 1.0004x; 1.0004x over previous
#include <cuda_runtime.h>
#include <math.h>
#include <stdint.h>

#define Dv   512
#define Nn   8192
#define K1   2560    // 5*D  (Agg_0..3, x)
#define QK   2048    // 4*D  (q,k,v,skip)

// ---- static scratch (no allocations allowed) ----
__device__ float g_H0[(size_t)Nn * K1];     // 80 MB  [N, 5D]
__device__ float g_ho[(size_t)Nn * Dv];     // 16 MB  [N, D]
__device__ float g_qkvs[(size_t)Nn * QK];   // 64 MB  [N, 4, D] = q|k|v|skip

__device__ __forceinline__ int lower_bound_i(const int* __restrict__ a, int n, int key) {
    int lo = 0, hi = n;
    while (lo < hi) { int m = (lo + hi) >> 1; if (a[m] < key) lo = m + 1; else hi = m; }
    return lo;
}

__device__ __forceinline__ float tf32r(float x) {
    uint32_t y;
    asm("cvt.rna.tf32.f32 %0, %1;" : "=r"(y) : "f"(x));
    return __uint_as_float(y);
}

__device__ __forceinline__ void mma8(float* d, const uint32_t* a, const uint32_t* b) {
    asm volatile(
        "mma.sync.aligned.m16n8k8.row.col.f32.tf32.tf32.f32 "
        "{%0,%1,%2,%3}, {%4,%5,%6,%7}, {%8,%9}, {%0,%1,%2,%3};"
        : "+f"(d[0]), "+f"(d[1]), "+f"(d[2]), "+f"(d[3])
        : "r"(a[0]), "r"(a[1]), "r"(a[2]), "r"(a[3]), "r"(b[0]), "r"(b[1]));
}

// ============================================================
// Kernel 1: per-node per-relation neighbor mean -> H0 [N, 5D]
// ============================================================
__global__ __launch_bounds__(128) void agg_kernel(
    const float* __restrict__ x,
    const int*   __restrict__ src,
    const int*   __restrict__ dst,
    const int*   __restrict__ et,
    int E)
{
    int i = blockIdx.x;
    int t = threadIdx.x;
    __shared__ int s_lo, s_nE;
    __shared__ int s_src[32], s_rel[32];
    __shared__ int s_cnt[4];

    if (t == 0) {
        int lo = lower_bound_i(dst, E, i);
        int hi = lower_bound_i(dst, E, i + 1);
        s_lo = lo;
        int n = hi - lo; if (n > 32) n = 32;
        s_nE = n;
    }
    if (t < 4) s_cnt[t] = 0;
    __syncthreads();
    int nE = s_nE, lo = s_lo;
    if (t < nE) {
        s_src[t] = src[lo + t];
        int r = et[lo + t];
        s_rel[t] = r;
        atomicAdd(&s_cnt[r], 1);
    }
    __syncthreads();

    int d0 = t * 4;
    float4 a0 = {0,0,0,0}, a1 = a0, a2 = a0, a3 = a0;
    for (int e = 0; e < nE; e++) {
        int s = s_src[e];
        float4 v = *reinterpret_cast<const float4*>(x + (size_t)s * Dv + d0);
        int r = s_rel[e];
        if (r == 0)      { a0.x += v.x; a0.y += v.y; a0.z += v.z; a0.w += v.w; }
        else if (r == 1) { a1.x += v.x; a1.y += v.y; a1.z += v.z; a1.w += v.w; }
        else if (r == 2) { a2.x += v.x; a2.y += v.y; a2.z += v.z; a2.w += v.w; }
        else             { a3.x += v.x; a3.y += v.y; a3.z += v.z; a3.w += v.w; }
    }
    float i0 = 1.f / fmaxf((float)s_cnt[0], 1.f);
    float i1 = 1.f / fmaxf((float)s_cnt[1], 1.f);
    float i2 = 1.f / fmaxf((float)s_cnt[2], 1.f);
    float i3 = 1.f / fmaxf((float)s_cnt[3], 1.f);
    float* H = g_H0 + (size_t)i * K1;
    a0.x*=i0; a0.y*=i0; a0.z*=i0; a0.w*=i0;
    a1.x*=i1; a1.y*=i1; a1.z*=i1; a1.w*=i1;
    a2.x*=i2; a2.y*=i2; a2.z*=i2; a2.w*=i2;
    a3.x*=i3; a3.y*=i3; a3.z*=i3; a3.w*=i3;
    *reinterpret_cast<float4*>(H + 0*Dv + d0) = a0;
    *reinterpret_cast<float4*>(H + 1*Dv + d0) = a1;
    *reinterpret_cast<float4*>(H + 2*Dv + d0) = a2;
    *reinterpret_cast<float4*>(H + 3*Dv + d0) = a3;
    float4 xv = *reinterpret_cast<const float4*>(x + (size_t)i * Dv + d0);
    *reinterpret_cast<float4*>(H + 4*Dv + d0) = xv;
}

// ============================================================
// TF32 tensor-core GEMM tiles: 128x128x32, 8 warps (2x4),
// warp tile 64x32 via m16n8k8 mma.
// As layout [m][k], lead 36 (frag reads bank-conflict-free).
// Bs layout [k][n], lead 132 (frag reads bank-conflict-free).
// ============================================================
#define LDA 36
#define LDB 132

// Kernel 2: ho = H0 [8192x2560] @ [W_rel;W_root] [2560x512] + b
__global__ __launch_bounds__(256) void gemm_rgcn(
    const float* __restrict__ Wrel,   // [2048, 512]
    const float* __restrict__ Wroot,  // [512, 512]
    const float* __restrict__ bias)   // [512]
{
    __shared__ float As[128 * LDA];
    __shared__ float Bs[32 * LDB];
    const float* A = g_H0;
    float* C = g_ho;
    const int K = K1;
    int tid = threadIdx.x;
    int n0 = blockIdx.x * 128, m0 = blockIdx.y * 128;
    int wid = tid >> 5, lane = tid & 31;
    int wr = wid >> 2, wc = wid & 3;
    int g = lane >> 2, tig = lane & 3;
    float acc[4][4][4] = {};
    float4 ra[4], rb[4];

    #pragma unroll
    for (int s = 0; s < 4; s++) {
        int idx = tid + 256 * s;
        int m = idx >> 3, kq = (idx & 7) * 4;
        ra[s] = *(const float4*)(A + (size_t)(m0 + m) * K + kq);
    }
    #pragma unroll
    for (int s = 0; s < 4; s++) {
        int idx = tid + 256 * s;
        int k = idx >> 5, n4 = (idx & 31) * 4;
        rb[s] = *(const float4*)(Wrel + (size_t)k * Dv + n0 + n4);
    }

    const int ITER = K / 32;
    for (int it = 0; it < ITER; ++it) {
        #pragma unroll
        for (int s = 0; s < 4; s++) {
            int idx = tid + 256 * s;
            int m = idx >> 3, kq = (idx & 7) * 4;
            float* p = &As[m * LDA + kq];
            p[0] = tf32r(ra[s].x); p[1] = tf32r(ra[s].y);
            p[2] = tf32r(ra[s].z); p[3] = tf32r(ra[s].w);
        }
        #pragma unroll
        for (int s = 0; s < 4; s++) {
            int idx = tid + 256 * s;
            int k = idx >> 5, n4 = (idx & 31) * 4;
            float* p = &Bs[k * LDB + n4];
            p[0] = tf32r(rb[s].x); p[1] = tf32r(rb[s].y);
            p[2] = tf32r(rb[s].z); p[3] = tf32r(rb[s].w);
        }
        __syncthreads();
        if (it + 1 < ITER) {
            int k0n = (it + 1) * 32;
            #pragma unroll
            for (int s = 0; s < 4; s++) {
                int idx = tid + 256 * s;
                int m = idx >> 3, kq = (idx & 7) * 4;
                ra[s] = *(const float4*)(A + (size_t)(m0 + m) * K + k0n + kq);
            }
            #pragma unroll
            for (int s = 0; s < 4; s++) {
                int idx = tid + 256 * s;
                int k = idx >> 5, n4 = (idx & 31) * 4;
                int kk = k0n + k;
                const float* bp = (kk < 2048) ? (Wrel + (size_t)kk * Dv)
                                              : (Wroot + (size_t)(kk - 2048) * Dv);
                rb[s] = *(const float4*)(bp + n0 + n4);
            }
        }
        #pragma unroll
        for (int ks = 0; ks < 4; ks++) {
            int kb = ks * 8;
            uint32_t af[4][4], bf[4][2];
            #pragma unroll
            for (int mt = 0; mt < 4; mt++) {
                int mr = wr * 64 + mt * 16;
                af[mt][0] = __float_as_uint(As[(mr + g)     * LDA + kb + tig]);
                af[mt][1] = __float_as_uint(As[(mr + g + 8) * LDA + kb + tig]);
                af[mt][2] = __float_as_uint(As[(mr + g)     * LDA + kb + tig + 4]);
                af[mt][3] = __float_as_uint(As[(mr + g + 8) * LDA + kb + tig + 4]);
            }
            #pragma unroll
            for (int nt = 0; nt < 4; nt++) {
                int nc = wc * 32 + nt * 8;
                bf[nt][0] = __float_as_uint(Bs[(kb + tig)     * LDB + nc + g]);
                bf[nt][1] = __float_as_uint(Bs[(kb + tig + 4) * LDB + nc + g]);
            }
            #pragma unroll
            for (int mt = 0; mt < 4; mt++)
                #pragma unroll
                for (int nt = 0; nt < 4; nt++)
                    mma8(acc[mt][nt], af[mt], bf[nt]);
        }
        __syncthreads();
    }
    #pragma unroll
    for (int mt = 0; mt < 4; mt++) {
        int mr = m0 + wr * 64 + mt * 16;
        #pragma unroll
        for (int nt = 0; nt < 4; nt++) {
            int nc = n0 + wc * 32 + nt * 8 + 2 * tig;
            float b0 = bias[nc], b1 = bias[nc + 1];
            float2 v0 = {acc[mt][nt][0] + b0, acc[mt][nt][1] + b1};
            float2 v1 = {acc[mt][nt][2] + b0, acc[mt][nt][3] + b1};
            *(float2*)(C + (size_t)(mr + g)     * Dv + nc) = v0;
            *(float2*)(C + (size_t)(mr + g + 8) * Dv + nc) = v1;
        }
    }
}

// Kernel 3: [q|k|v|skip] = ho [8192x512] @ W [512x2048] + b
__global__ __launch_bounds__(256) void gemm_qkvs(
    const float* __restrict__ Wq, const float* __restrict__ Wk,
    const float* __restrict__ Wv, const float* __restrict__ Ws,
    const float* __restrict__ bq, const float* __restrict__ bk,
    const float* __restrict__ bv, const float* __restrict__ bs)
{
    __shared__ float As[128 * LDA];
    __shared__ float Bs[32 * LDB];
    const float* A = g_ho;
    float* C = g_qkvs;
    const int K = Dv;
    int tid = threadIdx.x;
    int n0 = blockIdx.x * 128, m0 = blockIdx.y * 128;
    int wsel = n0 >> 9;
    const float* W  = (wsel == 0) ? Wq : (wsel == 1) ? Wk : (wsel == 2) ? Wv : Ws;
    const float* bb = (wsel == 0) ? bq : (wsel == 1) ? bk : (wsel == 2) ? bv : bs;
    int bc0 = n0 & 511;
    int wid = tid >> 5, lane = tid & 31;
    int wr = wid >> 2, wc = wid & 3;
    int g = lane >> 2, tig = lane & 3;
    float acc[4][4][4] = {};
    float4 ra[4], rb[4];

    #pragma unroll
    for (int s = 0; s < 4; s++) {
        int idx = tid + 256 * s;
        int m = idx >> 3, kq = (idx & 7) * 4;
        ra[s] = *(const float4*)(A + (size_t)(m0 + m) * K + kq);
    }
    #pragma unroll
    for (int s = 0; s < 4; s++) {
        int idx = tid + 256 * s;
        int k = idx >> 5, n4 = (idx & 31) * 4;
        rb[s] = *(const float4*)(W + (size_t)k * Dv + bc0 + n4);
    }

    const int ITER = K / 32;   // 16
    for (int it = 0; it < ITER; ++it) {
        #pragma unroll
        for (int s = 0; s < 4; s++) {
            int idx = tid + 256 * s;
            int m = idx >> 3, kq = (idx & 7) * 4;
            float* p = &As[m * LDA + kq];
            p[0] = tf32r(ra[s].x); p[1] = tf32r(ra[s].y);
            p[2] = tf32r(ra[s].z); p[3] = tf32r(ra[s].w);
        }
        #pragma unroll
        for (int s = 0; s < 4; s++) {
            int idx = tid + 256 * s;
            int k = idx >> 5, n4 = (idx & 31) * 4;
            float* p = &Bs[k * LDB + n4];
            p[0] = tf32r(rb[s].x); p[1] = tf32r(rb[s].y);
            p[2] = tf32r(rb[s].z); p[3] = tf32r(rb[s].w);
        }
        __syncthreads();
        if (it + 1 < ITER) {
            int k0n = (it + 1) * 32;
            #pragma unroll
            for (int s = 0; s < 4; s++) {
                int idx = tid + 256 * s;
                int m = idx >> 3, kq = (idx & 7) * 4;
                ra[s] = *(const float4*)(A + (size_t)(m0 + m) * K + k0n + kq);
            }
            #pragma unroll
            for (int s = 0; s < 4; s++) {
                int idx = tid + 256 * s;
                int k = idx >> 5, n4 = (idx & 31) * 4;
                rb[s] = *(const float4*)(W + (size_t)(k0n + k) * Dv + bc0 + n4);
            }
        }
        #pragma unroll
        for (int ks = 0; ks < 4; ks++) {
            int kb = ks * 8;
            uint32_t af[4][4], bf[4][2];
            #pragma unroll
            for (int mt = 0; mt < 4; mt++) {
                int mr = wr * 64 + mt * 16;
                af[mt][0] = __float_as_uint(As[(mr + g)     * LDA + kb + tig]);
                af[mt][1] = __float_as_uint(As[(mr + g + 8) * LDA + kb + tig]);
                af[mt][2] = __float_as_uint(As[(mr + g)     * LDA + kb + tig + 4]);
                af[mt][3] = __float_as_uint(As[(mr + g + 8) * LDA + kb + tig + 4]);
            }
            #pragma unroll
            for (int nt = 0; nt < 4; nt++) {
                int nc = wc * 32 + nt * 8;
                bf[nt][0] = __float_as_uint(Bs[(kb + tig)     * LDB + nc + g]);
                bf[nt][1] = __float_as_uint(Bs[(kb + tig + 4) * LDB + nc + g]);
            }
            #pragma unroll
            for (int mt = 0; mt < 4; mt++)
                #pragma unroll
                for (int nt = 0; nt < 4; nt++)
                    mma8(acc[mt][nt], af[mt], bf[nt]);
        }
        __syncthreads();
    }
    #pragma unroll
    for (int mt = 0; mt < 4; mt++) {
        int mr = m0 + wr * 64 + mt * 16;
        #pragma unroll
        for (int nt = 0; nt < 4; nt++) {
            int colw = wc * 32 + nt * 8 + 2 * tig;
            int nc = n0 + colw;            // global col in [0,2048)
            int bi = bc0 + colw;           // index into 512-wide bias
            float b0 = bb[bi], b1 = bb[bi + 1];
            float2 v0 = {acc[mt][nt][0] + b0, acc[mt][nt][1] + b1};
            float2 v1 = {acc[mt][nt][2] + b0, acc[mt][nt][3] + b1};
            *(float2*)(C + (size_t)(mr + g)     * QK + nc) = v0;
            *(float2*)(C + (size_t)(mr + g + 8) * QK + nc) = v1;
        }
    }
}

// ============================================================
// Kernel 4: per-node attention softmax + skip + leaky + residual + LN
// ============================================================
__global__ __launch_bounds__(256) void attn_kernel(
    const float* __restrict__ x,
    const int*   __restrict__ src,
    const int*   __restrict__ dst,
    int E,
    const float* __restrict__ gamma,
    const float* __restrict__ beta,
    float* __restrict__ out)
{
    int i = blockIdx.x;
    int t = threadIdx.x;
    __shared__ float q_s[512];
    __shared__ float logit[32];
    __shared__ float alpha[32];
    __shared__ int   s_src[32];
    __shared__ int   s_lo, s_nE;
    __shared__ float red1[8], red2[8];
    __shared__ float s_mu, s_rstd;
    const float* qkvs = g_qkvs;

    if (t == 0) {
        int lo = lower_bound_i(dst, E, i);
        int hi = lower_bound_i(dst, E, i + 1);
        s_lo = lo; int n = hi - lo; if (n > 32) n = 32; s_nE = n;
    }
    __syncthreads();
    int nE = s_nE, lo = s_lo;
    q_s[t]       = qkvs[(size_t)i * QK + t];
    q_s[t + 256] = qkvs[(size_t)i * QK + t + 256];
    if (t < nE) s_src[t] = src[lo + t];
    __syncthreads();

    int wid = t >> 5, lane = t & 31;
    for (int e = wid; e < nE; e += 8) {
        const float* kp = qkvs + (size_t)s_src[e] * QK + 512;
        float sum = 0.f;
        #pragma unroll
        for (int c = 0; c < 4; c++) {
            int d = c * 128 + lane * 4;
            float4 qa = *(const float4*)&q_s[d];
            float4 kb = *(const float4*)(kp + d);
            sum += qa.x*kb.x + qa.y*kb.y + qa.z*kb.z + qa.w*kb.w;
        }
        #pragma unroll
        for (int o = 16; o; o >>= 1) sum += __shfl_xor_sync(0xffffffffu, sum, o);
        if (lane == 0) logit[e] = sum * 0.04419417382415922f; // 1/sqrt(512)
    }
    __syncthreads();
    if (t == 0) {
        float mx = -INFINITY;
        for (int e = 0; e < nE; e++) mx = fmaxf(mx, logit[e]);
        if (nE == 0 || !isfinite(mx)) mx = 0.f;
        float den = 0.f;
        for (int e = 0; e < nE; e++) { float ex = expf(logit[e] - mx); alpha[e] = ex; den += ex; }
        float inv = 1.f / fmaxf(den, 1e-16f);
        for (int e = 0; e < nE; e++) alpha[e] *= inv;
    }
    __syncthreads();

    int d0 = t * 2;
    float acc0 = 0.f, acc1 = 0.f;
    for (int e = 0; e < nE; e++) {
        float a = alpha[e];
        float2 v = *(const float2*)(qkvs + (size_t)s_src[e] * QK + 1024 + d0);
        acc0 += a * v.x; acc1 += a * v.y;
    }
    float2 sk = *(const float2*)(qkvs + (size_t)i * QK + 1536 + d0);
    float h0 = acc0 + sk.x, h1 = acc1 + sk.y;
    h0 = h0 > 0.f ? h0 : 0.01f * h0;
    h1 = h1 > 0.f ? h1 : 0.01f * h1;
    float2 xv = *(const float2*)(x + (size_t)i * Dv + d0);
    float o0 = xv.x + h0, o1 = xv.y + h1;

    float s1 = o0 + o1, s2 = o0*o0 + o1*o1;
    #pragma unroll
    for (int o = 16; o; o >>= 1) {
        s1 += __shfl_xor_sync(0xffffffffu, s1, o);
        s2 += __shfl_xor_sync(0xffffffffu, s2, o);
    }
    if (lane == 0) { red1[wid] = s1; red2[wid] = s2; }
    __syncthreads();
    if (t == 0) {
        float S1 = 0.f, S2 = 0.f;
        #pragma unroll
        for (int w = 0; w < 8; w++) { S1 += red1[w]; S2 += red2[w]; }
        float mu = S1 / 512.f;
        float var = S2 / 512.f - mu * mu;
        s_mu = mu; s_rstd = rsqrtf(var + 1e-5f);
    }
    __syncthreads();
    float mu = s_mu, rs = s_rstd;
    float2 ov;
    ov.x = (o0 - mu) * rs * gamma[d0]     + beta[d0];
    ov.y = (o1 - mu) * rs * gamma[d0 + 1] + beta[d0 + 1];
    *(float2*)(out + (size_t)i * Dv + d0) = ov;
}

// scalar loss output (always 0 in eval path)
__global__ void tail_kernel(float* out, int out_size) {
    int idx = Nn * Dv + threadIdx.x;
    if (idx < out_size) out[idx] = 0.f;
}

extern "C" void kernel_launch(void* const* d_in, const int* in_sizes, int n_in,
                              void* d_out, int out_size) {
    const float* x     = (const float*)d_in[0];
    const int*   ei    = (const int*)  d_in[1];
    const int*   et    = (const int*)  d_in[2];
    const float* Wrel  = (const float*)d_in[3];
    const float* Wroot = (const float*)d_in[4];
    const float* brg   = (const float*)d_in[5];
    const float* Wq    = (const float*)d_in[6];
    const float* bq    = (const float*)d_in[7];
    const float* Wk    = (const float*)d_in[8];
    const float* bk    = (const float*)d_in[9];
    const float* Wv    = (const float*)d_in[10];
    const float* bv    = (const float*)d_in[11];
    const float* Wsk   = (const float*)d_in[12];
    const float* bsk   = (const float*)d_in[13];
    const float* gamma = (const float*)d_in[14];
    const float* beta  = (const float*)d_in[15];
    float* out = (float*)d_out;

    int E = in_sizes[2];
    const int* src = ei;
    const int* dst = ei + E;

    agg_kernel<<<Nn, 128>>>(x, src, dst, et, E);
    gemm_rgcn<<<dim3(Dv / 128, Nn / 128), 256>>>(Wrel, Wroot, brg);
    gemm_qkvs<<<dim3(QK / 128, Nn / 128), 256>>>(Wq, Wk, Wv, Wsk, bq, bk, bv, bsk);
    attn_kernel<<<Nn, 256>>>(x, src, dst, E, gamma, beta, out);
    if (out_size > Nn * Dv) tail_kernel<<<1, 256>>>(out, out_size);
}

// round 8
// speedup vs baseline: 1.6934x; 1.6928x over previous
#include <cuda_runtime.h>
#include <cuda_bf16.h>
#include <math.h>
#include <stdint.h>

#define Dv   512
#define Nn   8192
#define K1   2560    // 5*D  (Agg_0..3, x)
#define QK   2048    // 4*D  (q,k,v,skip)

// ---- static scratch (no allocations allowed) ----
__device__ __nv_bfloat16 g_H0[(size_t)Nn * K1];   // 40 MB  [N, 5D] bf16
__device__ __nv_bfloat16 g_ho[(size_t)Nn * Dv];   //  8 MB  [N, D]  bf16
__device__ float         g_qkvs[(size_t)Nn * QK]; // 64 MB  [N, 4, D] fp32

__device__ __forceinline__ int lower_bound_i(const int* __restrict__ a, int n, int key) {
    int lo = 0, hi = n;
    while (lo < hi) { int m = (lo + hi) >> 1; if (a[m] < key) lo = m + 1; else hi = m; }
    return lo;
}

__device__ __forceinline__ uint32_t packbf(float lo, float hi) {
    __nv_bfloat162 h = __floats2bfloat162_rn(lo, hi);   // x (low) = lo
    return reinterpret_cast<uint32_t&>(h);
}

__device__ __forceinline__ uint2 f4_to_bf(float4 v) {
    uint2 r; r.x = packbf(v.x, v.y); r.y = packbf(v.z, v.w); return r;
}

// m16n8k16 bf16 mma, fp32 accum
__device__ __forceinline__ void mma16(float* d, const uint32_t* a, const uint32_t* b) {
    asm volatile(
        "mma.sync.aligned.m16n8k16.row.col.f32.bf16.bf16.f32 "
        "{%0,%1,%2,%3}, {%4,%5,%6,%7}, {%8,%9}, {%0,%1,%2,%3};"
        : "+f"(d[0]), "+f"(d[1]), "+f"(d[2]), "+f"(d[3])
        : "r"(a[0]), "r"(a[1]), "r"(a[2]), "r"(a[3]), "r"(b[0]), "r"(b[1]));
}

// ============================================================
// Kernel 1: per-node per-relation neighbor mean -> H0 [N, 5D] (bf16)
// ============================================================
__global__ __launch_bounds__(128) void agg_kernel(
    const float* __restrict__ x,
    const int*   __restrict__ src,
    const int*   __restrict__ dst,
    const int*   __restrict__ et,
    int E)
{
    int i = blockIdx.x;
    int t = threadIdx.x;
    __shared__ int s_lo, s_nE;
    __shared__ int s_src[32], s_rel[32];
    __shared__ int s_cnt[4];

    if (t == 0) {
        int lo = lower_bound_i(dst, E, i);
        int hi = lower_bound_i(dst, E, i + 1);
        s_lo = lo;
        int n = hi - lo; if (n > 32) n = 32;
        s_nE = n;
    }
    if (t < 4) s_cnt[t] = 0;
    __syncthreads();
    int nE = s_nE, lo = s_lo;
    if (t < nE) {
        s_src[t] = src[lo + t];
        int r = et[lo + t];
        s_rel[t] = r;
        atomicAdd(&s_cnt[r], 1);
    }
    __syncthreads();

    int d0 = t * 4;
    float4 a0 = {0,0,0,0}, a1 = a0, a2 = a0, a3 = a0;
    for (int e = 0; e < nE; e++) {
        int s = s_src[e];
        float4 v = *reinterpret_cast<const float4*>(x + (size_t)s * Dv + d0);
        int r = s_rel[e];
        if (r == 0)      { a0.x += v.x; a0.y += v.y; a0.z += v.z; a0.w += v.w; }
        else if (r == 1) { a1.x += v.x; a1.y += v.y; a1.z += v.z; a1.w += v.w; }
        else if (r == 2) { a2.x += v.x; a2.y += v.y; a2.z += v.z; a2.w += v.w; }
        else             { a3.x += v.x; a3.y += v.y; a3.z += v.z; a3.w += v.w; }
    }
    float i0 = 1.f / fmaxf((float)s_cnt[0], 1.f);
    float i1 = 1.f / fmaxf((float)s_cnt[1], 1.f);
    float i2 = 1.f / fmaxf((float)s_cnt[2], 1.f);
    float i3 = 1.f / fmaxf((float)s_cnt[3], 1.f);
    a0.x*=i0; a0.y*=i0; a0.z*=i0; a0.w*=i0;
    a1.x*=i1; a1.y*=i1; a1.z*=i1; a1.w*=i1;
    a2.x*=i2; a2.y*=i2; a2.z*=i2; a2.w*=i2;
    a3.x*=i3; a3.y*=i3; a3.z*=i3; a3.w*=i3;
    __nv_bfloat16* H = g_H0 + (size_t)i * K1;
    *reinterpret_cast<uint2*>(H + 0*Dv + d0) = f4_to_bf(a0);
    *reinterpret_cast<uint2*>(H + 1*Dv + d0) = f4_to_bf(a1);
    *reinterpret_cast<uint2*>(H + 2*Dv + d0) = f4_to_bf(a2);
    *reinterpret_cast<uint2*>(H + 3*Dv + d0) = f4_to_bf(a3);
    float4 xv = *reinterpret_cast<const float4*>(x + (size_t)i * Dv + d0);
    *reinterpret_cast<uint2*>(H + 4*Dv + d0) = f4_to_bf(xv);
}

// ============================================================
// bf16 GEMM tiles: 128x128x32, 8 warps (2x4), warp tile 64x32
// As: bf16-pairs as uint32, [m][k/2], lead 20 words (bank 20g+tig distinct)
// Bs: k-pair-packed uint32 [k/2][n], lead 136 words (bank 8tig+g distinct)
// ============================================================
#define LDA32 20
#define LDB32 136

// Kernel 2: ho = H0 [8192x2560] @ [W_rel;W_root] [2560x512] + b   (bf16 out)
__global__ __launch_bounds__(256) void gemm_rgcn(
    const float* __restrict__ Wrel,   // [2048, 512]
    const float* __restrict__ Wroot,  // [512, 512]
    const float* __restrict__ bias)   // [512]
{
    __shared__ uint32_t As[128 * LDA32];
    __shared__ uint32_t Bs[16 * LDB32];
    const __nv_bfloat16* A = g_H0;
    __nv_bfloat16* C = g_ho;
    const int K = K1;
    int tid = threadIdx.x;
    int n0 = blockIdx.x * 128, m0 = blockIdx.y * 128;
    int wid = tid >> 5, lane = tid & 31;
    int wr = wid >> 2, wc = wid & 3;
    int g = lane >> 2, tig = lane & 3;
    float acc[4][4][4] = {};
    uint4 ra[2]; float4 rb0[2], rb1[2];

    #pragma unroll
    for (int s = 0; s < 2; s++) {
        int v = tid + 256 * s; int row = v >> 2, kw = v & 3;
        ra[s] = *(const uint4*)(A + (size_t)(m0 + row) * K + kw * 8);
    }
    #pragma unroll
    for (int s = 0; s < 2; s++) {
        int v = tid + 256 * s; int kp = v >> 5, n4 = (v & 31) * 4;
        int kk = 2 * kp;
        const float* bp = (kk < 2048) ? (Wrel + (size_t)kk * Dv)
                                      : (Wroot + (size_t)(kk - 2048) * Dv);
        rb0[s] = *(const float4*)(bp + n0 + n4);
        rb1[s] = *(const float4*)(bp + Dv + n0 + n4);
    }

    const int ITER = K / 32;   // 80
    for (int it = 0; it < ITER; ++it) {
        #pragma unroll
        for (int s = 0; s < 2; s++) {
            int v = tid + 256 * s; int row = v >> 2, kw = v & 3;
            *(uint4*)(&As[row * LDA32 + kw * 4]) = ra[s];
        }
        #pragma unroll
        for (int s = 0; s < 2; s++) {
            int v = tid + 256 * s; int kp = v >> 5, n4 = (v & 31) * 4;
            uint4 pk;
            pk.x = packbf(rb0[s].x, rb1[s].x);
            pk.y = packbf(rb0[s].y, rb1[s].y);
            pk.z = packbf(rb0[s].z, rb1[s].z);
            pk.w = packbf(rb0[s].w, rb1[s].w);
            *(uint4*)(&Bs[kp * LDB32 + n4]) = pk;
        }
        __syncthreads();
        if (it + 1 < ITER) {
            int k0n = (it + 1) * 32;
            #pragma unroll
            for (int s = 0; s < 2; s++) {
                int v = tid + 256 * s; int row = v >> 2, kw = v & 3;
                ra[s] = *(const uint4*)(A + (size_t)(m0 + row) * K + k0n + kw * 8);
            }
            #pragma unroll
            for (int s = 0; s < 2; s++) {
                int v = tid + 256 * s; int kp = v >> 5, n4 = (v & 31) * 4;
                int kk = k0n + 2 * kp;
                const float* bp = (kk < 2048) ? (Wrel + (size_t)kk * Dv)
                                              : (Wroot + (size_t)(kk - 2048) * Dv);
                rb0[s] = *(const float4*)(bp + n0 + n4);
                rb1[s] = *(const float4*)(bp + Dv + n0 + n4);
            }
        }
        #pragma unroll
        for (int ks = 0; ks < 2; ks++) {
            uint32_t af[4][4], bf[4][2];
            #pragma unroll
            for (int mt = 0; mt < 4; mt++) {
                int mr = wr * 64 + mt * 16;
                af[mt][0] = As[(mr + g)     * LDA32 + ks * 8 + tig];
                af[mt][1] = As[(mr + g + 8) * LDA32 + ks * 8 + tig];
                af[mt][2] = As[(mr + g)     * LDA32 + ks * 8 + tig + 4];
                af[mt][3] = As[(mr + g + 8) * LDA32 + ks * 8 + tig + 4];
            }
            #pragma unroll
            for (int nt = 0; nt < 4; nt++) {
                int nc = wc * 32 + nt * 8;
                bf[nt][0] = Bs[(ks * 8 + tig)     * LDB32 + nc + g];
                bf[nt][1] = Bs[(ks * 8 + tig + 4) * LDB32 + nc + g];
            }
            #pragma unroll
            for (int mt = 0; mt < 4; mt++)
                #pragma unroll
                for (int nt = 0; nt < 4; nt++)
                    mma16(acc[mt][nt], af[mt], bf[nt]);
        }
        __syncthreads();
    }
    #pragma unroll
    for (int mt = 0; mt < 4; mt++) {
        int mr = m0 + wr * 64 + mt * 16;
        #pragma unroll
        for (int nt = 0; nt < 4; nt++) {
            int nc = n0 + wc * 32 + nt * 8 + 2 * tig;
            float b0 = bias[nc], b1 = bias[nc + 1];
            uint32_t v0 = packbf(acc[mt][nt][0] + b0, acc[mt][nt][1] + b1);
            uint32_t v1 = packbf(acc[mt][nt][2] + b0, acc[mt][nt][3] + b1);
            *(uint32_t*)(C + (size_t)(mr + g)     * Dv + nc) = v0;
            *(uint32_t*)(C + (size_t)(mr + g + 8) * Dv + nc) = v1;
        }
    }
}

// Kernel 3: [q|k|v|skip] = ho [8192x512] @ W [512x2048] + b  (fp32 out)
__global__ __launch_bounds__(256) void gemm_qkvs(
    const float* __restrict__ Wq, const float* __restrict__ Wk,
    const float* __restrict__ Wv, const float* __restrict__ Ws,
    const float* __restrict__ bq, const float* __restrict__ bk,
    const float* __restrict__ bv, const float* __restrict__ bs)
{
    __shared__ uint32_t As[128 * LDA32];
    __shared__ uint32_t Bs[16 * LDB32];
    const __nv_bfloat16* A = g_ho;
    float* C = g_qkvs;
    const int K = Dv;
    int tid = threadIdx.x;
    int n0 = blockIdx.x * 128, m0 = blockIdx.y * 128;
    int wsel = n0 >> 9;
    const float* W  = (wsel == 0) ? Wq : (wsel == 1) ? Wk : (wsel == 2) ? Wv : Ws;
    const float* bb = (wsel == 0) ? bq : (wsel == 1) ? bk : (wsel == 2) ? bv : bs;
    int bc0 = n0 & 511;
    int wid = tid >> 5, lane = tid & 31;
    int wr = wid >> 2, wc = wid & 3;
    int g = lane >> 2, tig = lane & 3;
    float acc[4][4][4] = {};
    uint4 ra[2]; float4 rb0[2], rb1[2];

    #pragma unroll
    for (int s = 0; s < 2; s++) {
        int v = tid + 256 * s; int row = v >> 2, kw = v & 3;
        ra[s] = *(const uint4*)(A + (size_t)(m0 + row) * K + kw * 8);
    }
    #pragma unroll
    for (int s = 0; s < 2; s++) {
        int v = tid + 256 * s; int kp = v >> 5, n4 = (v & 31) * 4;
        const float* bp = W + (size_t)(2 * kp) * Dv;
        rb0[s] = *(const float4*)(bp + bc0 + n4);
        rb1[s] = *(const float4*)(bp + Dv + bc0 + n4);
    }

    const int ITER = K / 32;   // 16
    for (int it = 0; it < ITER; ++it) {
        #pragma unroll
        for (int s = 0; s < 2; s++) {
            int v = tid + 256 * s; int row = v >> 2, kw = v & 3;
            *(uint4*)(&As[row * LDA32 + kw * 4]) = ra[s];
        }
        #pragma unroll
        for (int s = 0; s < 2; s++) {
            int v = tid + 256 * s; int kp = v >> 5, n4 = (v & 31) * 4;
            uint4 pk;
            pk.x = packbf(rb0[s].x, rb1[s].x);
            pk.y = packbf(rb0[s].y, rb1[s].y);
            pk.z = packbf(rb0[s].z, rb1[s].z);
            pk.w = packbf(rb0[s].w, rb1[s].w);
            *(uint4*)(&Bs[kp * LDB32 + n4]) = pk;
        }
        __syncthreads();
        if (it + 1 < ITER) {
            int k0n = (it + 1) * 32;
            #pragma unroll
            for (int s = 0; s < 2; s++) {
                int v = tid + 256 * s; int row = v >> 2, kw = v & 3;
                ra[s] = *(const uint4*)(A + (size_t)(m0 + row) * K + k0n + kw * 8);
            }
            #pragma unroll
            for (int s = 0; s < 2; s++) {
                int v = tid + 256 * s; int kp = v >> 5, n4 = (v & 31) * 4;
                const float* bp = W + (size_t)(k0n + 2 * kp) * Dv;
                rb0[s] = *(const float4*)(bp + bc0 + n4);
                rb1[s] = *(const float4*)(bp + Dv + bc0 + n4);
            }
        }
        #pragma unroll
        for (int ks = 0; ks < 2; ks++) {
            uint32_t af[4][4], bf[4][2];
            #pragma unroll
            for (int mt = 0; mt < 4; mt++) {
                int mr = wr * 64 + mt * 16;
                af[mt][0] = As[(mr + g)     * LDA32 + ks * 8 + tig];
                af[mt][1] = As[(mr + g + 8) * LDA32 + ks * 8 + tig];
                af[mt][2] = As[(mr + g)     * LDA32 + ks * 8 + tig + 4];
                af[mt][3] = As[(mr + g + 8) * LDA32 + ks * 8 + tig + 4];
            }
            #pragma unroll
            for (int nt = 0; nt < 4; nt++) {
                int nc = wc * 32 + nt * 8;
                bf[nt][0] = Bs[(ks * 8 + tig)     * LDB32 + nc + g];
                bf[nt][1] = Bs[(ks * 8 + tig + 4) * LDB32 + nc + g];
            }
            #pragma unroll
            for (int mt = 0; mt < 4; mt++)
                #pragma unroll
                for (int nt = 0; nt < 4; nt++)
                    mma16(acc[mt][nt], af[mt], bf[nt]);
        }
        __syncthreads();
    }
    #pragma unroll
    for (int mt = 0; mt < 4; mt++) {
        int mr = m0 + wr * 64 + mt * 16;
        #pragma unroll
        for (int nt = 0; nt < 4; nt++) {
            int colw = wc * 32 + nt * 8 + 2 * tig;
            int nc = n0 + colw;
            int bi = bc0 + colw;
            float b0 = bb[bi], b1 = bb[bi + 1];
            float2 v0 = {acc[mt][nt][0] + b0, acc[mt][nt][1] + b1};
            float2 v1 = {acc[mt][nt][2] + b0, acc[mt][nt][3] + b1};
            *(float2*)(C + (size_t)(mr + g)     * QK + nc) = v0;
            *(float2*)(C + (size_t)(mr + g + 8) * QK + nc) = v1;
        }
    }
}

// ============================================================
// Kernel 4: attention softmax + skip + leaky + residual + LN
// 128 threads/block, 4 dims/thread, warp-parallel softmax
// ============================================================
__global__ __launch_bounds__(128) void attn_kernel(
    const float* __restrict__ x,
    const int*   __restrict__ src,
    const int*   __restrict__ dst,
    int E,
    const float* __restrict__ gamma,
    const float* __restrict__ beta,
    float* __restrict__ out)
{
    int i = blockIdx.x;
    int t = threadIdx.x;     // 0..127
    __shared__ float q_s[512];
    __shared__ float logit[32];
    __shared__ float alpha_s[32];
    __shared__ int   s_src[32];
    __shared__ int   s_lo, s_nE;
    __shared__ float red1[4], red2[4];
    __shared__ float s_mu, s_rstd;
    const float* qkvs = g_qkvs;

    if (t == 0) {
        int lo = lower_bound_i(dst, E, i);
        int hi = lower_bound_i(dst, E, i + 1);
        s_lo = lo; int n = hi - lo; if (n > 32) n = 32; s_nE = n;
    }
    __syncthreads();
    int nE = s_nE, lo = s_lo;
    int d0 = t * 4;
    *(float4*)&q_s[d0] = *(const float4*)(qkvs + (size_t)i * QK + d0);
    if (t < nE) s_src[t] = src[lo + t];
    __syncthreads();

    int wid = t >> 5, lane = t & 31;
    for (int e = wid; e < nE; e += 4) {
        const float* kp = qkvs + (size_t)s_src[e] * QK + 512;
        float sum = 0.f;
        #pragma unroll
        for (int c = 0; c < 4; c++) {
            int d = c * 128 + lane * 4;
            float4 qa = *(const float4*)&q_s[d];
            float4 kb = *(const float4*)(kp + d);
            sum += qa.x*kb.x + qa.y*kb.y + qa.z*kb.z + qa.w*kb.w;
        }
        #pragma unroll
        for (int o = 16; o; o >>= 1) sum += __shfl_xor_sync(0xffffffffu, sum, o);
        if (lane == 0) logit[e] = sum * 0.04419417382415922f; // 1/sqrt(512)
    }
    __syncthreads();
    if (wid == 0) {
        float l = (lane < nE) ? logit[lane] : -INFINITY;
        float mx = l;
        #pragma unroll
        for (int o = 16; o; o >>= 1) mx = fmaxf(mx, __shfl_xor_sync(0xffffffffu, mx, o));
        if (!isfinite(mx)) mx = 0.f;
        float ex = (lane < nE) ? expf(l - mx) : 0.f;
        float den = ex;
        #pragma unroll
        for (int o = 16; o; o >>= 1) den += __shfl_xor_sync(0xffffffffu, den, o);
        float inv = 1.f / fmaxf(den, 1e-16f);
        alpha_s[lane] = ex * inv;
    }
    __syncthreads();

    float4 accv = {0,0,0,0};
    for (int e = 0; e < nE; e++) {
        float a = alpha_s[e];
        float4 v = *(const float4*)(qkvs + (size_t)s_src[e] * QK + 1024 + d0);
        accv.x += a * v.x; accv.y += a * v.y; accv.z += a * v.z; accv.w += a * v.w;
    }
    float4 sk = *(const float4*)(qkvs + (size_t)i * QK + 1536 + d0);
    float h0 = accv.x + sk.x, h1 = accv.y + sk.y;
    float h2 = accv.z + sk.z, h3 = accv.w + sk.w;
    h0 = h0 > 0.f ? h0 : 0.01f * h0;
    h1 = h1 > 0.f ? h1 : 0.01f * h1;
    h2 = h2 > 0.f ? h2 : 0.01f * h2;
    h3 = h3 > 0.f ? h3 : 0.01f * h3;
    float4 xv = *(const float4*)(x + (size_t)i * Dv + d0);
    float o0 = xv.x + h0, o1 = xv.y + h1, o2 = xv.z + h2, o3 = xv.w + h3;

    float s1 = o0 + o1 + o2 + o3;
    float s2 = o0*o0 + o1*o1 + o2*o2 + o3*o3;
    #pragma unroll
    for (int o = 16; o; o >>= 1) {
        s1 += __shfl_xor_sync(0xffffffffu, s1, o);
        s2 += __shfl_xor_sync(0xffffffffu, s2, o);
    }
    if (lane == 0) { red1[wid] = s1; red2[wid] = s2; }
    __syncthreads();
    if (t == 0) {
        float S1 = red1[0] + red1[1] + red1[2] + red1[3];
        float S2 = red2[0] + red2[1] + red2[2] + red2[3];
        float mu = S1 / 512.f;
        float var = S2 / 512.f - mu * mu;
        s_mu = mu; s_rstd = rsqrtf(var + 1e-5f);
    }
    __syncthreads();
    float mu = s_mu, rs = s_rstd;
    float4 gm = *(const float4*)(gamma + d0);
    float4 bt = *(const float4*)(beta + d0);
    float4 ov;
    ov.x = (o0 - mu) * rs * gm.x + bt.x;
    ov.y = (o1 - mu) * rs * gm.y + bt.y;
    ov.z = (o2 - mu) * rs * gm.z + bt.z;
    ov.w = (o3 - mu) * rs * gm.w + bt.w;
    *(float4*)(out + (size_t)i * Dv + d0) = ov;
}

// scalar loss output (always 0 in eval path)
__global__ void tail_kernel(float* out, int out_size) {
    int idx = Nn * Dv + threadIdx.x;
    if (idx < out_size) out[idx] = 0.f;
}

extern "C" void kernel_launch(void* const* d_in, const int* in_sizes, int n_in,
                              void* d_out, int out_size) {
    const float* x     = (const float*)d_in[0];
    const int*   ei    = (const int*)  d_in[1];
    const int*   et    = (const int*)  d_in[2];
    const float* Wrel  = (const float*)d_in[3];
    const float* Wroot = (const float*)d_in[4];
    const float* brg   = (const float*)d_in[5];
    const float* Wq    = (const float*)d_in[6];
    const float* bq    = (const float*)d_in[7];
    const float* Wk    = (const float*)d_in[8];
    const float* bk    = (const float*)d_in[9];
    const float* Wv    = (const float*)d_in[10];
    const float* bv    = (const float*)d_in[11];
    const float* Wsk   = (const float*)d_in[12];
    const float* bsk   = (const float*)d_in[13];
    const float* gamma = (const float*)d_in[14];
    const float* beta  = (const float*)d_in[15];
    float* out = (float*)d_out;

    int E = in_sizes[2];
    const int* src = ei;
    const int* dst = ei + E;

    agg_kernel<<<Nn, 128>>>(x, src, dst, et, E);
    gemm_rgcn<<<dim3(Dv / 128, Nn / 128), 256>>>(Wrel, Wroot, brg);
    gemm_qkvs<<<dim3(QK / 128, Nn / 128), 256>>>(Wq, Wk, Wv, Wsk, bq, bk, bv, bsk);
    attn_kernel<<<Nn, 128>>>(x, src, dst, E, gamma, beta, out);
    if (out_size > Nn * Dv) tail_kernel<<<1, 256>>>(out, out_size);
}

// round 10
// speedup vs baseline: 1.7746x; 1.0480x over previous
#include <cuda_runtime.h>
#include <cuda_bf16.h>
#include <math.h>
#include <stdint.h>

#define Dv   512
#define Nn   8192
#define K1   2560    // 5*D  (Agg_0..3, x)
#define QK   2048    // 4*D  (q,k,v,skip)

// ---- static scratch (no allocations allowed) ----
__device__ __nv_bfloat16 g_H0[(size_t)Nn * K1];   // 40 MB  [N, 5D] bf16
__device__ __nv_bfloat16 g_ho[(size_t)Nn * Dv];   //  8 MB  [N, D]  bf16
__device__ float         g_qkvs[(size_t)Nn * QK]; // 64 MB  [N, 4, D] fp32
__device__ uint32_t      g_Wp1[(size_t)(K1/2) * Dv];      // 2.6 MB packed bf16 [W_rel;W_root]
__device__ uint32_t      g_Wp2[(size_t)4 * (Dv/2) * Dv];  // 2.1 MB packed bf16 q|k|v|skip

__device__ __forceinline__ int lower_bound_i(const int* __restrict__ a, int n, int key) {
    int lo = 0, hi = n;
    while (lo < hi) { int m = (lo + hi) >> 1; if (a[m] < key) lo = m + 1; else hi = m; }
    return lo;
}

__device__ __forceinline__ uint32_t packbf(float lo, float hi) {
    __nv_bfloat162 h = __floats2bfloat162_rn(lo, hi);   // x (low) = lo
    return reinterpret_cast<uint32_t&>(h);
}

__device__ __forceinline__ uint2 f4_to_bf(float4 v) {
    uint2 r; r.x = packbf(v.x, v.y); r.y = packbf(v.z, v.w); return r;
}

// m16n8k16 bf16 mma, fp32 accum
__device__ __forceinline__ void mma16(float* d, const uint32_t* a, const uint32_t* b) {
    asm volatile(
        "mma.sync.aligned.m16n8k16.row.col.f32.bf16.bf16.f32 "
        "{%0,%1,%2,%3}, {%4,%5,%6,%7}, {%8,%9}, {%0,%1,%2,%3};"
        : "+f"(d[0]), "+f"(d[1]), "+f"(d[2]), "+f"(d[3])
        : "r"(a[0]), "r"(a[1]), "r"(a[2]), "r"(a[3]), "r"(b[0]), "r"(b[1]));
}

__device__ __forceinline__ void cpa16(void* smem, const void* g) {
    uint32_t s = (uint32_t)__cvta_generic_to_shared(smem);
    asm volatile("cp.async.ca.shared.global [%0], [%1], 16;" :: "r"(s), "l"(g));
}
#define CP_COMMIT() asm volatile("cp.async.commit_group;")
#define CP_WAIT0()  asm volatile("cp.async.wait_group 0;")

// ============================================================
// Kernel 0: pack weights fp32 -> k-pair-packed bf16 uint32
// ============================================================
__global__ __launch_bounds__(512) void pack_weights(
    const float* __restrict__ Wrel, const float* __restrict__ Wroot,
    const float* __restrict__ Wq, const float* __restrict__ Wk,
    const float* __restrict__ Wv, const float* __restrict__ Ws)
{
    int r = blockIdx.x;
    int n = threadIdx.x;
    if (r < K1 / 2) {
        int kk = 2 * r;
        const float* p0 = (kk < 2048) ? (Wrel + (size_t)kk * Dv) : (Wroot + (size_t)(kk - 2048) * Dv);
        const float* p1 = p0 + Dv;
        g_Wp1[(size_t)r * Dv + n] = packbf(p0[n], p1[n]);
    } else {
        int rp = r - K1 / 2;
        int w = rp >> 8, kp = rp & 255;
        const float* W = (w == 0) ? Wq : (w == 1) ? Wk : (w == 2) ? Wv : Ws;
        const float* p0 = W + (size_t)(2 * kp) * Dv;
        g_Wp2[(size_t)rp * Dv + n] = packbf(p0[n], p0[Dv + n]);
    }
}

// ============================================================
// Kernel 1: per-node per-relation neighbor mean -> H0 [N, 5D] (bf16)
// ============================================================
__global__ __launch_bounds__(128) void agg_kernel(
    const float* __restrict__ x,
    const int*   __restrict__ src,
    const int*   __restrict__ dst,
    const int*   __restrict__ et,
    int E)
{
    int i = blockIdx.x;
    int t = threadIdx.x;
    __shared__ int s_lo, s_nE;
    __shared__ int s_src[32], s_rel[32];
    __shared__ int s_cnt[4];

    if (t == 0) {
        int lo = lower_bound_i(dst, E, i);
        int hi = lower_bound_i(dst, E, i + 1);
        s_lo = lo;
        int n = hi - lo; if (n > 32) n = 32;
        s_nE = n;
    }
    if (t < 4) s_cnt[t] = 0;
    __syncthreads();
    int nE = s_nE, lo = s_lo;
    if (t < nE) {
        s_src[t] = src[lo + t];
        int r = et[lo + t];
        s_rel[t] = r;
        atomicAdd(&s_cnt[r], 1);
    }
    __syncthreads();

    int d0 = t * 4;
    float4 a0 = {0,0,0,0}, a1 = a0, a2 = a0, a3 = a0;
    for (int e = 0; e < nE; e++) {
        int s = s_src[e];
        float4 v = *reinterpret_cast<const float4*>(x + (size_t)s * Dv + d0);
        int r = s_rel[e];
        if (r == 0)      { a0.x += v.x; a0.y += v.y; a0.z += v.z; a0.w += v.w; }
        else if (r == 1) { a1.x += v.x; a1.y += v.y; a1.z += v.z; a1.w += v.w; }
        else if (r == 2) { a2.x += v.x; a2.y += v.y; a2.z += v.z; a2.w += v.w; }
        else             { a3.x += v.x; a3.y += v.y; a3.z += v.z; a3.w += v.w; }
    }
    float i0 = 1.f / fmaxf((float)s_cnt[0], 1.f);
    float i1 = 1.f / fmaxf((float)s_cnt[1], 1.f);
    float i2 = 1.f / fmaxf((float)s_cnt[2], 1.f);
    float i3 = 1.f / fmaxf((float)s_cnt[3], 1.f);
    a0.x*=i0; a0.y*=i0; a0.z*=i0; a0.w*=i0;
    a1.x*=i1; a1.y*=i1; a1.z*=i1; a1.w*=i1;
    a2.x*=i2; a2.y*=i2; a2.z*=i2; a2.w*=i2;
    a3.x*=i3; a3.y*=i3; a3.z*=i3; a3.w*=i3;
    __nv_bfloat16* H = g_H0 + (size_t)i * K1;
    *reinterpret_cast<uint2*>(H + 0*Dv + d0) = f4_to_bf(a0);
    *reinterpret_cast<uint2*>(H + 1*Dv + d0) = f4_to_bf(a1);
    *reinterpret_cast<uint2*>(H + 2*Dv + d0) = f4_to_bf(a2);
    *reinterpret_cast<uint2*>(H + 3*Dv + d0) = f4_to_bf(a3);
    float4 xv = *reinterpret_cast<const float4*>(x + (size_t)i * Dv + d0);
    *reinterpret_cast<uint2*>(H + 4*Dv + d0) = f4_to_bf(xv);
}

// ============================================================
// bf16 GEMM tiles: 128x128x32, 8 warps (2x4), warp tile 64x32,
// cp.async 2-stage pipeline; A bf16 scratch, B pre-packed uint32.
// As: [m][k/2] uint32, lead 20 words. Bs: [k/2][n], lead 136 words.
// Global A bf16 offset per copy = a_kw * 2 (4 words = 8 bf16).
// ============================================================
#define LDA32 20
#define LDB32 136

// Kernel 2: ho = H0 [8192x2560] @ packed W1 + b   (bf16 out)
__global__ __launch_bounds__(256) void gemm_rgcn(const float* __restrict__ bias)
{
    __shared__ uint32_t As[2][128 * LDA32];
    __shared__ uint32_t Bs[2][16 * LDB32];
    const __nv_bfloat16* A = g_H0;
    const uint32_t* Wp = g_Wp1;
    __nv_bfloat16* C = g_ho;
    const int K = K1;
    int tid = threadIdx.x;
    int n0 = blockIdx.x * 128, m0 = blockIdx.y * 128;
    int wid = tid >> 5, lane = tid & 31;
    int wr = wid >> 2, wc = wid & 3;
    int g = lane >> 2, tig = lane & 3;
    float acc[4][4][4] = {};

    // per-thread load descriptors (word offsets in smem)
    int a_row0 = tid >> 2,            a_kw0 = (tid & 3) * 4;
    int a_row1 = (tid + 256) >> 2,    a_kw1 = a_kw0;
    int b_kp0  = tid >> 5,            b_n0w = (tid & 31) * 4;
    int b_kp1  = (tid + 256) >> 5,    b_n1w = b_n0w;

    const int ITER = K / 32;   // 80
    {
        cpa16(&As[0][a_row0 * LDA32 + a_kw0], A + (size_t)(m0 + a_row0) * K + a_kw0 * 2);
        cpa16(&As[0][a_row1 * LDA32 + a_kw1], A + (size_t)(m0 + a_row1) * K + a_kw1 * 2);
        cpa16(&Bs[0][b_kp0 * LDB32 + b_n0w], Wp + (size_t)b_kp0 * Dv + n0 + b_n0w);
        cpa16(&Bs[0][b_kp1 * LDB32 + b_n1w], Wp + (size_t)b_kp1 * Dv + n0 + b_n1w);
        CP_COMMIT();
    }
    for (int it = 0; it < ITER; ++it) {
        CP_WAIT0();
        __syncthreads();
        if (it + 1 < ITER) {
            int st = (it + 1) & 1;
            int kb = (it + 1) * 32;
            int kpb = (it + 1) * 16;
            cpa16(&As[st][a_row0 * LDA32 + a_kw0], A + (size_t)(m0 + a_row0) * K + kb + a_kw0 * 2);
            cpa16(&As[st][a_row1 * LDA32 + a_kw1], A + (size_t)(m0 + a_row1) * K + kb + a_kw1 * 2);
            cpa16(&Bs[st][b_kp0 * LDB32 + b_n0w], Wp + (size_t)(kpb + b_kp0) * Dv + n0 + b_n0w);
            cpa16(&Bs[st][b_kp1 * LDB32 + b_n1w], Wp + (size_t)(kpb + b_kp1) * Dv + n0 + b_n1w);
            CP_COMMIT();
        }
        int st = it & 1;
        #pragma unroll
        for (int ks = 0; ks < 2; ks++) {
            uint32_t af[4][4], bf[4][2];
            #pragma unroll
            for (int mt = 0; mt < 4; mt++) {
                int mr = wr * 64 + mt * 16;
                af[mt][0] = As[st][(mr + g)     * LDA32 + ks * 8 + tig];
                af[mt][1] = As[st][(mr + g + 8) * LDA32 + ks * 8 + tig];
                af[mt][2] = As[st][(mr + g)     * LDA32 + ks * 8 + tig + 4];
                af[mt][3] = As[st][(mr + g + 8) * LDA32 + ks * 8 + tig + 4];
            }
            #pragma unroll
            for (int nt = 0; nt < 4; nt++) {
                int nc = wc * 32 + nt * 8;
                bf[nt][0] = Bs[st][(ks * 8 + tig)     * LDB32 + nc + g];
                bf[nt][1] = Bs[st][(ks * 8 + tig + 4) * LDB32 + nc + g];
            }
            #pragma unroll
            for (int mt = 0; mt < 4; mt++)
                #pragma unroll
                for (int nt = 0; nt < 4; nt++)
                    mma16(acc[mt][nt], af[mt], bf[nt]);
        }
    }
    #pragma unroll
    for (int mt = 0; mt < 4; mt++) {
        int mr = m0 + wr * 64 + mt * 16;
        #pragma unroll
        for (int nt = 0; nt < 4; nt++) {
            int nc = n0 + wc * 32 + nt * 8 + 2 * tig;
            float b0 = bias[nc], b1 = bias[nc + 1];
            uint32_t v0 = packbf(acc[mt][nt][0] + b0, acc[mt][nt][1] + b1);
            uint32_t v1 = packbf(acc[mt][nt][2] + b0, acc[mt][nt][3] + b1);
            *(uint32_t*)(C + (size_t)(mr + g)     * Dv + nc) = v0;
            *(uint32_t*)(C + (size_t)(mr + g + 8) * Dv + nc) = v1;
        }
    }
}

// Kernel 3: [q|k|v|skip] = ho [8192x512] @ packed W2 + b  (fp32 out)
__global__ __launch_bounds__(256) void gemm_qkvs(
    const float* __restrict__ bq, const float* __restrict__ bk,
    const float* __restrict__ bv, const float* __restrict__ bs)
{
    __shared__ uint32_t As[2][128 * LDA32];
    __shared__ uint32_t Bs[2][16 * LDB32];
    const __nv_bfloat16* A = g_ho;
    float* C = g_qkvs;
    const int K = Dv;
    int tid = threadIdx.x;
    int n0 = blockIdx.x * 128, m0 = blockIdx.y * 128;
    int wsel = n0 >> 9;
    const uint32_t* Wp = g_Wp2 + (size_t)wsel * (Dv / 2) * Dv;
    const float* bb = (wsel == 0) ? bq : (wsel == 1) ? bk : (wsel == 2) ? bv : bs;
    int bc0 = n0 & 511;
    int wid = tid >> 5, lane = tid & 31;
    int wr = wid >> 2, wc = wid & 3;
    int g = lane >> 2, tig = lane & 3;
    float acc[4][4][4] = {};

    int a_row0 = tid >> 2,         a_kw0 = (tid & 3) * 4;
    int a_row1 = (tid + 256) >> 2, a_kw1 = a_kw0;
    int b_kp0  = tid >> 5,         b_n0w = (tid & 31) * 4;
    int b_kp1  = (tid + 256) >> 5, b_n1w = b_n0w;

    const int ITER = K / 32;   // 16
    {
        cpa16(&As[0][a_row0 * LDA32 + a_kw0], A + (size_t)(m0 + a_row0) * K + a_kw0 * 2);
        cpa16(&As[0][a_row1 * LDA32 + a_kw1], A + (size_t)(m0 + a_row1) * K + a_kw1 * 2);
        cpa16(&Bs[0][b_kp0 * LDB32 + b_n0w], Wp + (size_t)b_kp0 * Dv + bc0 + b_n0w);
        cpa16(&Bs[0][b_kp1 * LDB32 + b_n1w], Wp + (size_t)b_kp1 * Dv + bc0 + b_n1w);
        CP_COMMIT();
    }
    for (int it = 0; it < ITER; ++it) {
        CP_WAIT0();
        __syncthreads();
        if (it + 1 < ITER) {
            int st = (it + 1) & 1;
            int kb = (it + 1) * 32;
            int kpb = (it + 1) * 16;
            cpa16(&As[st][a_row0 * LDA32 + a_kw0], A + (size_t)(m0 + a_row0) * K + kb + a_kw0 * 2);
            cpa16(&As[st][a_row1 * LDA32 + a_kw1], A + (size_t)(m0 + a_row1) * K + kb + a_kw1 * 2);
            cpa16(&Bs[st][b_kp0 * LDB32 + b_n0w], Wp + (size_t)(kpb + b_kp0) * Dv + bc0 + b_n0w);
            cpa16(&Bs[st][b_kp1 * LDB32 + b_n1w], Wp + (size_t)(kpb + b_kp1) * Dv + bc0 + b_n1w);
            CP_COMMIT();
        }
        int st = it & 1;
        #pragma unroll
        for (int ks = 0; ks < 2; ks++) {
            uint32_t af[4][4], bf[4][2];
            #pragma unroll
            for (int mt = 0; mt < 4; mt++) {
                int mr = wr * 64 + mt * 16;
                af[mt][0] = As[st][(mr + g)     * LDA32 + ks * 8 + tig];
                af[mt][1] = As[st][(mr + g + 8) * LDA32 + ks * 8 + tig];
                af[mt][2] = As[st][(mr + g)     * LDA32 + ks * 8 + tig + 4];
                af[mt][3] = As[st][(mr + g + 8) * LDA32 + ks * 8 + tig + 4];
            }
            #pragma unroll
            for (int nt = 0; nt < 4; nt++) {
                int nc = wc * 32 + nt * 8;
                bf[nt][0] = Bs[st][(ks * 8 + tig)     * LDB32 + nc + g];
                bf[nt][1] = Bs[st][(ks * 8 + tig + 4) * LDB32 + nc + g];
            }
            #pragma unroll
            for (int mt = 0; mt < 4; mt++)
                #pragma unroll
                for (int nt = 0; nt < 4; nt++)
                    mma16(acc[mt][nt], af[mt], bf[nt]);
        }
    }
    #pragma unroll
    for (int mt = 0; mt < 4; mt++) {
        int mr = m0 + wr * 64 + mt * 16;
        #pragma unroll
        for (int nt = 0; nt < 4; nt++) {
            int colw = wc * 32 + nt * 8 + 2 * tig;
            int nc = n0 + colw;
            int bi = bc0 + colw;
            float b0 = bb[bi], b1 = bb[bi + 1];
            float2 v0 = {acc[mt][nt][0] + b0, acc[mt][nt][1] + b1};
            float2 v1 = {acc[mt][nt][2] + b0, acc[mt][nt][3] + b1};
            *(float2*)(C + (size_t)(mr + g)     * QK + nc) = v0;
            *(float2*)(C + (size_t)(mr + g + 8) * QK + nc) = v1;
        }
    }
}

// ============================================================
// Kernel 4: attention softmax + skip + leaky + residual + LN
// ============================================================
__global__ __launch_bounds__(128) void attn_kernel(
    const float* __restrict__ x,
    const int*   __restrict__ src,
    const int*   __restrict__ dst,
    int E,
    const float* __restrict__ gamma,
    const float* __restrict__ beta,
    float* __restrict__ out)
{
    int i = blockIdx.x;
    int t = threadIdx.x;     // 0..127
    __shared__ float q_s[512];
    __shared__ float logit[32];
    __shared__ float alpha_s[32];
    __shared__ int   s_src[32];
    __shared__ int   s_lo, s_nE;
    __shared__ float red1[4], red2[4];
    __shared__ float s_mu, s_rstd;
    const float* qkvs = g_qkvs;

    if (t == 0) {
        int lo = lower_bound_i(dst, E, i);
        int hi = lower_bound_i(dst, E, i + 1);
        s_lo = lo; int n = hi - lo; if (n > 32) n = 32; s_nE = n;
    }
    __syncthreads();
    int nE = s_nE, lo = s_lo;
    int d0 = t * 4;
    *(float4*)&q_s[d0] = *(const float4*)(qkvs + (size_t)i * QK + d0);
    if (t < nE) s_src[t] = src[lo + t];
    __syncthreads();

    int wid = t >> 5, lane = t & 31;
    for (int e = wid; e < nE; e += 4) {
        const float* kp = qkvs + (size_t)s_src[e] * QK + 512;
        float sum = 0.f;
        #pragma unroll
        for (int c = 0; c < 4; c++) {
            int d = c * 128 + lane * 4;
            float4 qa = *(const float4*)&q_s[d];
            float4 kb = *(const float4*)(kp + d);
            sum += qa.x*kb.x + qa.y*kb.y + qa.z*kb.z + qa.w*kb.w;
        }
        #pragma unroll
        for (int o = 16; o; o >>= 1) sum += __shfl_xor_sync(0xffffffffu, sum, o);
        if (lane == 0) logit[e] = sum * 0.04419417382415922f; // 1/sqrt(512)
    }
    __syncthreads();
    if (wid == 0) {
        float l = (lane < nE) ? logit[lane] : -INFINITY;
        float mx = l;
        #pragma unroll
        for (int o = 16; o; o >>= 1) mx = fmaxf(mx, __shfl_xor_sync(0xffffffffu, mx, o));
        if (!isfinite(mx)) mx = 0.f;
        float ex = (lane < nE) ? expf(l - mx) : 0.f;
        float den = ex;
        #pragma unroll
        for (int o = 16; o; o >>= 1) den += __shfl_xor_sync(0xffffffffu, den, o);
        float inv = 1.f / fmaxf(den, 1e-16f);
        alpha_s[lane] = ex * inv;
    }
    __syncthreads();

    float4 accv = {0,0,0,0};
    for (int e = 0; e < nE; e++) {
        float a = alpha_s[e];
        float4 v = *(const float4*)(qkvs + (size_t)s_src[e] * QK + 1024 + d0);
        accv.x += a * v.x; accv.y += a * v.y; accv.z += a * v.z; accv.w += a * v.w;
    }
    float4 sk = *(const float4*)(qkvs + (size_t)i * QK + 1536 + d0);
    float h0 = accv.x + sk.x, h1 = accv.y + sk.y;
    float h2 = accv.z + sk.z, h3 = accv.w + sk.w;
    h0 = h0 > 0.f ? h0 : 0.01f * h0;
    h1 = h1 > 0.f ? h1 : 0.01f * h1;
    h2 = h2 > 0.f ? h2 : 0.01f * h2;
    h3 = h3 > 0.f ? h3 : 0.01f * h3;
    float4 xv = *(const float4*)(x + (size_t)i * Dv + d0);
    float o0 = xv.x + h0, o1 = xv.y + h1, o2 = xv.z + h2, o3 = xv.w + h3;

    float s1 = o0 + o1 + o2 + o3;
    float s2 = o0*o0 + o1*o1 + o2*o2 + o3*o3;
    #pragma unroll
    for (int o = 16; o; o >>= 1) {
        s1 += __shfl_xor_sync(0xffffffffu, s1, o);
        s2 += __shfl_xor_sync(0xffffffffu, s2, o);
    }
    if (lane == 0) { red1[wid] = s1; red2[wid] = s2; }
    __syncthreads();
    if (t == 0) {
        float S1 = red1[0] + red1[1] + red1[2] + red1[3];
        float S2 = red2[0] + red2[1] + red2[2] + red2[3];
        float mu = S1 / 512.f;
        float var = S2 / 512.f - mu * mu;
        s_mu = mu; s_rstd = rsqrtf(var + 1e-5f);
    }
    __syncthreads();
    float mu = s_mu, rs = s_rstd;
    float4 gm = *(const float4*)(gamma + d0);
    float4 bt = *(const float4*)(beta + d0);
    float4 ov;
    ov.x = (o0 - mu) * rs * gm.x + bt.x;
    ov.y = (o1 - mu) * rs * gm.y + bt.y;
    ov.z = (o2 - mu) * rs * gm.z + bt.z;
    ov.w = (o3 - mu) * rs * gm.w + bt.w;
    *(float4*)(out + (size_t)i * Dv + d0) = ov;
}

// scalar loss output (always 0 in eval path)
__global__ void tail_kernel(float* out, int out_size) {
    int idx = Nn * Dv + threadIdx.x;
    if (idx < out_size) out[idx] = 0.f;
}

extern "C" void kernel_launch(void* const* d_in, const int* in_sizes, int n_in,
                              void* d_out, int out_size) {
    const float* x     = (const float*)d_in[0];
    const int*   ei    = (const int*)  d_in[1];
    const int*   et    = (const int*)  d_in[2];
    const float* Wrel  = (const float*)d_in[3];
    const float* Wroot = (const float*)d_in[4];
    const float* brg   = (const float*)d_in[5];
    const float* Wq    = (const float*)d_in[6];
    const float* bq    = (const float*)d_in[7];
    const float* Wk    = (const float*)d_in[8];
    const float* bk    = (const float*)d_in[9];
    const float* Wv    = (const float*)d_in[10];
    const float* bv    = (const float*)d_in[11];
    const float* Wsk   = (const float*)d_in[12];
    const float* bsk   = (const float*)d_in[13];
    const float* gamma = (const float*)d_in[14];
    const float* beta  = (const float*)d_in[15];
    float* out = (float*)d_out;

    int E = in_sizes[2];
    const int* src = ei;
    const int* dst = ei + E;

    pack_weights<<<K1 / 2 + 4 * (Dv / 2), 512>>>(Wrel, Wroot, Wq, Wk, Wv, Wsk);
    agg_kernel<<<Nn, 128>>>(x, src, dst, et, E);
    gemm_rgcn<<<dim3(Dv / 128, Nn / 128), 256>>>(brg);
    gemm_qkvs<<<dim3(QK / 128, Nn / 128), 256>>>(bq, bk, bv, bsk);
    attn_kernel<<<Nn, 128>>>(x, src, dst, E, gamma, beta, out);
    if (out_size > Nn * Dv) tail_kernel<<<1, 256>>>(out, out_size);
}